// round 8
// baseline (speedup 1.0000x reference)
#include <cuda_runtime.h>
#include <cuda_fp16.h>
#include <cstdint>
#include <cstddef>

// ---------------------------------------------------------------------------
// Problem constants
// ---------------------------------------------------------------------------
#define M_ROWS 512
#define N_OUT  8192
#define K_IN   8192

#define TILE_M 128
#define TILE_N 128
#define TILE_K 64                 // K elements per chunk
#define NCH    (K_IN / TILE_K)    // 128 chunks

#define A_STAGE_BYTES (TILE_M * TILE_K * 2)   // 16384 fp16 swizzled
#define B_STAGE_BYTES (TILE_N * TILE_K * 2)   // 16384 fp16 swizzled
#define STAGE_BYTES (A_STAGE_BYTES + B_STAGE_BYTES)
#define STAGES 3
#define SMEM_TOTAL (STAGES * STAGE_BYTES)     // 98304

// ---------------------------------------------------------------------------
// Scratch (device global: allocation-free rule)
// ---------------------------------------------------------------------------
__device__ __half g_xh[(size_t)M_ROWS * K_IN];   // 8 MB fp16 x

// ---------------------------------------------------------------------------
// Helpers
// ---------------------------------------------------------------------------
__device__ __forceinline__ uint32_t smem_u32(const void* p) {
    uint32_t a;
    asm("{ .reg .u64 t; cvta.to.shared.u64 t, %1; cvt.u32.u64 %0, t; }"
        : "=r"(a) : "l"(p));
    return a;
}

__device__ __forceinline__ uint32_t sw128(uint32_t off) {
    return off ^ ((off >> 3) & 0x70);
}

__device__ __forceinline__ void cp_async16(uint32_t dst, const void* src) {
    asm volatile("cp.async.cg.shared.global [%0], [%1], 16;\n"
                 :: "r"(dst), "l"(src) : "memory");
}
#define CP_COMMIT() asm volatile("cp.async.commit_group;\n" ::: "memory")
#define CP_WAIT1()  asm volatile("cp.async.wait_group 1;\n" ::: "memory")

__device__ __forceinline__ void ldmatrix_x4(uint32_t* r, uint32_t addr) {
    asm volatile("ldmatrix.sync.aligned.m8n8.x4.shared.b16 {%0,%1,%2,%3}, [%4];\n"
                 : "=r"(r[0]), "=r"(r[1]), "=r"(r[2]), "=r"(r[3]) : "r"(addr));
}

__device__ __forceinline__ void sts64(uint32_t addr, uint32_t a, uint32_t b) {
    asm volatile("st.shared.v2.b32 [%0], {%1,%2};\n"
                 :: "r"(addr), "r"(a), "r"(b) : "memory");
}

__device__ __forceinline__ void mma16816(float* c, const uint32_t* a,
                                         const uint32_t* b) {
    asm volatile(
        "mma.sync.aligned.m16n8k16.row.col.f32.f16.f16.f32 "
        "{%0,%1,%2,%3}, {%4,%5,%6,%7}, {%8,%9}, {%0,%1,%2,%3};\n"
        : "+f"(c[0]), "+f"(c[1]), "+f"(c[2]), "+f"(c[3])
        : "r"(a[0]), "r"(a[1]), "r"(a[2]), "r"(a[3]), "r"(b[0]), "r"(b[1]));
}

// dequant one int4 (4 weights) -> 4 fp16, store 8B swizzled
__device__ __forceinline__ void cvt_sts(uint32_t addr, int4 q, float s) {
    __half2 a = __floats2half2_rn(s * (float)q.x, s * (float)q.y);
    __half2 b = __floats2half2_rn(s * (float)q.z, s * (float)q.w);
    sts64(addr, *reinterpret_cast<uint32_t*>(&a), *reinterpret_cast<uint32_t*>(&b));
}

// ---------------------------------------------------------------------------
// Kernel 1: x fp32 -> fp16
// ---------------------------------------------------------------------------
__global__ void __launch_bounds__(256) cvt_x_kernel(const float* __restrict__ x) {
    size_t t = (size_t)blockIdx.x * 256 + threadIdx.x;
    size_t base = t * 8;
    float4 a = *reinterpret_cast<const float4*>(x + base);
    float4 b = *reinterpret_cast<const float4*>(x + base + 4);
    __align__(16) __half h[8];
    h[0] = __float2half_rn(a.x); h[1] = __float2half_rn(a.y);
    h[2] = __float2half_rn(a.z); h[3] = __float2half_rn(a.w);
    h[4] = __float2half_rn(b.x); h[5] = __float2half_rn(b.y);
    h[6] = __float2half_rn(b.z); h[7] = __float2half_rn(b.w);
    *reinterpret_cast<uint4*>(g_xh + base) = *reinterpret_cast<uint4*>(h);
}

// ---------------------------------------------------------------------------
// Kernel 2: fused dequant + fp16 GEMM (mma.sync), 3-stage, 2 CTAs/SM
//   B path: LDG int32 -> convert -> STS fp16, pipelined inside the ks loop
// ---------------------------------------------------------------------------
__global__ void __launch_bounds__(256, 2) gemm_fused_kernel(
    const int* __restrict__ wq, const float* __restrict__ ws,
    float* __restrict__ out) {
    extern __shared__ char smem[];
    uint32_t sb = smem_u32(smem);

    int tid = threadIdx.x;
    int lid = tid & 31;
    int wid = tid >> 5;
    int wm = wid >> 1, wn = wid & 1;          // 4x2 warp grid
    int m_warp = wm * 32, n_warp = wn * 64;   // warp tile 32m x 64n

    int n0 = blockIdx.x * TILE_N;
    int m0 = blockIdx.y * TILE_M;
    int wsbase = (n0 >> 7) * (K_IN / 128);

    const __half* xh = g_xh;

    // B producer mapping: thread owns 8 int4 segs per chunk, batch b -> row brow+16b
    int brow = tid >> 4;                      // 0..15
    int bseg = tid & 15;                      // 16B segment in 256B row
    const int* wqt = wq + (size_t)(n0 + brow) * K_IN + bseg * 4;
    uint32_t bsts = (uint32_t)brow * 128 + bseg * 8;   // unswizzled tile offset

#define A_BASE(st) (sb + (uint32_t)(st) * STAGE_BYTES)
#define B_BASE(st) (sb + (uint32_t)(st) * STAGE_BYTES + A_STAGE_BYTES)
#define WROW (16 * K_IN)

#define LOAD_A(st, chunk) do {                                                \
    int k0h = (chunk) * TILE_K;                                               \
    uint32_t ab = A_BASE(st);                                                 \
    _Pragma("unroll")                                                         \
    for (int i = 0; i < 4; ++i) {                                             \
        int seg = tid + i * 256;                                              \
        int row = seg >> 3, c = seg & 7;                                      \
        cp_async16(ab + sw128((uint32_t)row * 128 + c * 16),                  \
                   xh + (size_t)(m0 + row) * K_IN + k0h + c * 8);             \
    }                                                                         \
} while (0)

#define COMPUTE_KS(ks) do {                                                   \
    uint32_t af[2][4];                                                        \
    _Pragma("unroll")                                                         \
    for (int mi = 0; mi < 2; ++mi) {                                          \
        uint32_t off = (uint32_t)(m_warp + mi * 16 + (lid & 15)) * 128        \
                     + (ks) * 32 + ((lid >> 4) << 4);                         \
        ldmatrix_x4(af[mi], aBase + sw128(off));                              \
    }                                                                         \
    uint32_t bf[8][2];                                                        \
    _Pragma("unroll")                                                         \
    for (int ntl = 0; ntl < 4; ++ntl) {                                       \
        uint32_t r[4];                                                        \
        uint32_t off = (uint32_t)(n_warp + ntl * 16 + (lid & 7)               \
                                  + ((lid >> 4) << 3)) * 128                  \
                     + (ks) * 32 + (((lid >> 3) & 1) << 4);                   \
        ldmatrix_x4(r, bBase + sw128(off));                                   \
        bf[2 * ntl][0] = r[0]; bf[2 * ntl][1] = r[1];                         \
        bf[2 * ntl + 1][0] = r[2]; bf[2 * ntl + 1][1] = r[3];                 \
    }                                                                         \
    _Pragma("unroll")                                                         \
    for (int mi = 0; mi < 2; ++mi)                                            \
        _Pragma("unroll")                                                     \
        for (int ni = 0; ni < 8; ++ni)                                        \
            mma16816(acc[mi][ni], af[mi], bf[ni]);                            \
} while (0)

    float acc[2][8][4];
#pragma unroll
    for (int mi = 0; mi < 2; ++mi)
#pragma unroll
        for (int ni = 0; ni < 8; ++ni)
#pragma unroll
            for (int j = 0; j < 4; ++j) acc[mi][ni][j] = 0.f;

    // ---- prologue ----
    LOAD_A(0, 0);
    CP_COMMIT();
    LOAD_A(1, 1);
    CP_COMMIT();
    {   // produce B(0) -> stage 0
        float s0 = ws[wsbase];
        uint32_t bb = B_BASE(0);
#pragma unroll
        for (int b = 0; b < 8; ++b) {
            int4 q = *reinterpret_cast<const int4*>(wqt + (size_t)b * WROW);
            cvt_sts(bb + sw128(bsts + b * (16 * 128)), q, s0);
        }
    }
    CP_WAIT1();              // A(0) landed
    __syncthreads();         // B(0) visible

    // ---- main loop ----
    int cur = 0, nxt = 1, nxt2 = 2;
#pragma unroll 1
    for (int it = 0; it < NCH; ++it) {
        if (it + 2 < NCH) LOAD_A(nxt2, it + 2);
        CP_COMMIT();

        uint32_t aBase = A_BASE(cur);
        uint32_t bBase = B_BASE(cur);
        uint32_t bb = B_BASE(nxt);

        bool hn = (it + 1 < NCH);
        const int* wp = wqt + (size_t)(it + 1) * TILE_K;
        float s = 0.f;
        int4 q0, q1, q2, q3, q4, q5, q6, q7;
        if (hn) {
            s = ws[wsbase + ((it + 1) >> 1)];
            q0 = *reinterpret_cast<const int4*>(wp);
            q1 = *reinterpret_cast<const int4*>(wp + (size_t)1 * WROW);
        }

        COMPUTE_KS(0);
        if (hn) {
            q2 = *reinterpret_cast<const int4*>(wp + (size_t)2 * WROW);
            q3 = *reinterpret_cast<const int4*>(wp + (size_t)3 * WROW);
        }
        COMPUTE_KS(1);
        if (hn) {
            cvt_sts(bb + sw128(bsts + 0 * 2048), q0, s);
            cvt_sts(bb + sw128(bsts + 1 * 2048), q1, s);
            q4 = *reinterpret_cast<const int4*>(wp + (size_t)4 * WROW);
            q5 = *reinterpret_cast<const int4*>(wp + (size_t)5 * WROW);
        }
        COMPUTE_KS(2);
        if (hn) {
            cvt_sts(bb + sw128(bsts + 2 * 2048), q2, s);
            cvt_sts(bb + sw128(bsts + 3 * 2048), q3, s);
            q6 = *reinterpret_cast<const int4*>(wp + (size_t)6 * WROW);
            q7 = *reinterpret_cast<const int4*>(wp + (size_t)7 * WROW);
        }
        COMPUTE_KS(3);
        if (hn) {
            cvt_sts(bb + sw128(bsts + 4 * 2048), q4, s);
            cvt_sts(bb + sw128(bsts + 5 * 2048), q5, s);
            cvt_sts(bb + sw128(bsts + 6 * 2048), q6, s);
            cvt_sts(bb + sw128(bsts + 7 * 2048), q7, s);
        }

        CP_WAIT1();
        __syncthreads();

        cur = (cur == STAGES - 1) ? 0 : cur + 1;
        nxt = (nxt == STAGES - 1) ? 0 : nxt + 1;
        nxt2 = (nxt2 == STAGES - 1) ? 0 : nxt2 + 1;
    }

    // ---- epilogue: fp32 direct ----
#pragma unroll
    for (int mi = 0; mi < 2; ++mi) {
#pragma unroll
        for (int ni = 0; ni < 8; ++ni) {
            int row = m0 + m_warp + mi * 16 + (lid >> 2);
            int col = n0 + n_warp + ni * 8 + ((lid & 3) << 1);
            float2 v0 = make_float2(acc[mi][ni][0], acc[mi][ni][1]);
            float2 v1 = make_float2(acc[mi][ni][2], acc[mi][ni][3]);
            *reinterpret_cast<float2*>(out + (size_t)row * N_OUT + col) = v0;
            *reinterpret_cast<float2*>(out + (size_t)(row + 8) * N_OUT + col) = v1;
        }
    }
}

// ---------------------------------------------------------------------------
// Launch
// ---------------------------------------------------------------------------
extern "C" void kernel_launch(void* const* d_in, const int* in_sizes, int n_in,
                              void* d_out, int out_size) {
    const float* x  = (const float*)d_in[0];
    const int*   wq = (const int*)d_in[1];     // int8 widened to int32 by harness
    const float* ws = (const float*)d_in[2];
    float* out = (float*)d_out;

    cvt_x_kernel<<<2048, 256>>>(x);

    cudaFuncSetAttribute(gemm_fused_kernel,
                         cudaFuncAttributeMaxDynamicSharedMemorySize, SMEM_TOTAL);
    dim3 grid(N_OUT / TILE_N, M_ROWS / TILE_M);  // (64, 4) = 256 CTAs
    gemm_fused_kernel<<<grid, 256, SMEM_TOTAL>>>(wq, ws, out);
}

// round 9
// speedup vs baseline: 1.0771x; 1.0771x over previous
#include <cuda_runtime.h>
#include <cuda_fp16.h>
#include <cstdint>
#include <cstddef>

// ---------------------------------------------------------------------------
// Problem constants
// ---------------------------------------------------------------------------
#define M_ROWS 512
#define N_OUT  8192
#define K_IN   8192

#define TILE_M 128
#define TILE_N 128
#define TILE_K 64                 // K elements per chunk
#define NCH    (K_IN / TILE_K)    // 128 chunks

#define A_STAGE_BYTES (TILE_M * TILE_K * 2)   // 16384 fp16 swizzled
#define B_STAGE_BYTES (TILE_N * TILE_K * 2)   // 16384 fp16 swizzled
#define STAGE_BYTES (A_STAGE_BYTES + B_STAGE_BYTES)
#define STAGES 3
#define SMEM_TOTAL (STAGES * STAGE_BYTES)     // 98304

// ---------------------------------------------------------------------------
// Scratch (device global: allocation-free rule)
// ---------------------------------------------------------------------------
__device__ __half g_xh[(size_t)M_ROWS * K_IN];   // 8 MB fp16 x

// ---------------------------------------------------------------------------
// Helpers
// ---------------------------------------------------------------------------
__device__ __forceinline__ uint32_t smem_u32(const void* p) {
    uint32_t a;
    asm("{ .reg .u64 t; cvta.to.shared.u64 t, %1; cvt.u32.u64 %0, t; }"
        : "=r"(a) : "l"(p));
    return a;
}

__device__ __forceinline__ uint32_t sw128(uint32_t off) {
    return off ^ ((off >> 3) & 0x70);
}

__device__ __forceinline__ void cp_async16(uint32_t dst, const void* src) {
    asm volatile("cp.async.cg.shared.global [%0], [%1], 16;\n"
                 :: "r"(dst), "l"(src) : "memory");
}
#define CP_COMMIT() asm volatile("cp.async.commit_group;\n" ::: "memory")
#define CP_WAIT1()  asm volatile("cp.async.wait_group 1;\n" ::: "memory")

__device__ __forceinline__ void ldmatrix_x4(uint32_t* r, uint32_t addr) {
    asm volatile("ldmatrix.sync.aligned.m8n8.x4.shared.b16 {%0,%1,%2,%3}, [%4];\n"
                 : "=r"(r[0]), "=r"(r[1]), "=r"(r[2]), "=r"(r[3]) : "r"(addr));
}

__device__ __forceinline__ void sts64(uint32_t addr, uint32_t a, uint32_t b) {
    asm volatile("st.shared.v2.b32 [%0], {%1,%2};\n"
                 :: "r"(addr), "r"(a), "r"(b) : "memory");
}

__device__ __forceinline__ void mma16816(float* c, const uint32_t* a,
                                         uint32_t b0, uint32_t b1) {
    asm volatile(
        "mma.sync.aligned.m16n8k16.row.col.f32.f16.f16.f32 "
        "{%0,%1,%2,%3}, {%4,%5,%6,%7}, {%8,%9}, {%0,%1,%2,%3};\n"
        : "+f"(c[0]), "+f"(c[1]), "+f"(c[2]), "+f"(c[3])
        : "r"(a[0]), "r"(a[1]), "r"(a[2]), "r"(a[3]), "r"(b0), "r"(b1));
}

// dequant one int4 (4 weights) -> 4 fp16, store 8B swizzled
__device__ __forceinline__ void cvt_sts(uint32_t addr, int4 q, float s) {
    __half2 a = __floats2half2_rn(s * (float)q.x, s * (float)q.y);
    __half2 b = __floats2half2_rn(s * (float)q.z, s * (float)q.w);
    sts64(addr, *reinterpret_cast<uint32_t*>(&a), *reinterpret_cast<uint32_t*>(&b));
}

// ---------------------------------------------------------------------------
// Kernel 1: x fp32 -> fp16
// ---------------------------------------------------------------------------
__global__ void __launch_bounds__(256) cvt_x_kernel(const float* __restrict__ x) {
    size_t t = (size_t)blockIdx.x * 256 + threadIdx.x;
    size_t base = t * 8;
    float4 a = *reinterpret_cast<const float4*>(x + base);
    float4 b = *reinterpret_cast<const float4*>(x + base + 4);
    __align__(16) __half h[8];
    h[0] = __float2half_rn(a.x); h[1] = __float2half_rn(a.y);
    h[2] = __float2half_rn(a.z); h[3] = __float2half_rn(a.w);
    h[4] = __float2half_rn(b.x); h[5] = __float2half_rn(b.y);
    h[6] = __float2half_rn(b.z); h[7] = __float2half_rn(b.w);
    *reinterpret_cast<uint4*>(g_xh + base) = *reinterpret_cast<uint4*>(h);
}

// ---------------------------------------------------------------------------
// Kernel 2: fused dequant + fp16 GEMM (mma.sync), 3-stage, 2 CTAs/SM
//   B path: LDG int32 -> convert -> STS fp16, interleaved with KS steps.
//   Register-lean: B fragments consumed immediately (no bf array).
// ---------------------------------------------------------------------------
__global__ void __launch_bounds__(256, 2) gemm_fused_kernel(
    const int* __restrict__ wq, const float* __restrict__ ws,
    float* __restrict__ out) {
    extern __shared__ char smem[];
    uint32_t sb = smem_u32(smem);

    int tid = threadIdx.x;
    int lid = tid & 31;
    int wid = tid >> 5;
    int m_warp = (wid >> 1) * 32;             // 4x2 warp grid
    int n_warp = (wid & 1) * 64;              // warp tile 32m x 64n

    int n0 = blockIdx.x * TILE_N;
    int m0 = blockIdx.y * TILE_M;
    const float* wsp = ws + (n0 >> 7) * (K_IN / 128);

    // A loader mapping: 4 x 16B segments per thread (row, col fixed)
    int arow = tid >> 3, acol = tid & 7;
    const __half* xp = g_xh + (size_t)(m0 + arow) * K_IN + acol * 8;
    uint32_t asts = sw128((uint32_t)arow * 128 + acol * 16);  // +4096 per i

    // B producer mapping: thread owns 8 int4 segs per chunk (rows brow+16b)
    int brow = tid >> 4, bseg = tid & 15;
    const int* wqt = wq + (size_t)(n0 + brow) * K_IN + bseg * 4;
    uint32_t bsts = (uint32_t)brow * 128 + bseg * 8;
#define WROW ((size_t)16 * K_IN)

#define A_BASE(st) (sb + (uint32_t)(st) * STAGE_BYTES)
#define B_BASE(st) (sb + (uint32_t)(st) * STAGE_BYTES + A_STAGE_BYTES)

    // A tile rows stride 8 per 256-thread sweep: 4 sweeps, +8 rows = +1024B
#define LOAD_A(st, chunk) do {                                                \
    const __half* _x = xp + (size_t)(chunk) * TILE_K;                         \
    uint32_t _ab = A_BASE(st) + asts;                                         \
    cp_async16(_ab,                      _x);                                 \
    cp_async16(_ab + (sw128(4096) - sw128(0)), _x + (size_t)32 * K_IN);       \
    cp_async16(_ab + (sw128(8192) - sw128(0)), _x + (size_t)64 * K_IN);       \
    cp_async16(_ab + (sw128(12288) - sw128(0)), _x + (size_t)96 * K_IN);      \
} while (0)
    // note: sw128(off + 4096k) == sw128(off) + 4096k (bits >=12 untouched)

#define COMPUTE_KS(ks) do {                                                   \
    uint32_t af[2][4];                                                        \
    _Pragma("unroll")                                                         \
    for (int mi = 0; mi < 2; ++mi) {                                          \
        uint32_t off = (uint32_t)(m_warp + mi * 16 + (lid & 15)) * 128        \
                     + (ks) * 32 + ((lid >> 4) << 4);                         \
        ldmatrix_x4(af[mi], aBase + sw128(off));                              \
    }                                                                         \
    _Pragma("unroll")                                                         \
    for (int ntl = 0; ntl < 4; ++ntl) {                                       \
        uint32_t r[4];                                                        \
        uint32_t off = (uint32_t)(n_warp + ntl * 16 + (lid & 7)               \
                                  + ((lid >> 4) << 3)) * 128                  \
                     + (ks) * 32 + (((lid >> 3) & 1) << 4);                   \
        ldmatrix_x4(r, bBase + sw128(off));                                   \
        _Pragma("unroll")                                                     \
        for (int mi = 0; mi < 2; ++mi) {                                      \
            mma16816(acc[mi][2 * ntl],     af[mi], r[0], r[1]);               \
            mma16816(acc[mi][2 * ntl + 1], af[mi], r[2], r[3]);               \
        }                                                                     \
    }                                                                         \
} while (0)

    float acc[2][8][4];
#pragma unroll
    for (int mi = 0; mi < 2; ++mi)
#pragma unroll
        for (int ni = 0; ni < 8; ++ni)
#pragma unroll
            for (int j = 0; j < 4; ++j) acc[mi][ni][j] = 0.f;

    // ---- prologue ----
    LOAD_A(0, 0);
    CP_COMMIT();
    LOAD_A(1, 1);
    CP_COMMIT();
    {   // produce B(0) -> stage 0
        float s0 = wsp[0];
        uint32_t bb = B_BASE(0);
#pragma unroll
        for (int b = 0; b < 8; ++b) {
            int4 q = *reinterpret_cast<const int4*>(wqt + (size_t)b * WROW);
            cvt_sts(bb + sw128(bsts + b * 2048), q, s0);
        }
    }
    CP_WAIT1();              // A(0) landed
    __syncthreads();         // B(0) visible

    // ---- main loop ----
    int cur = 0;
#pragma unroll 1
    for (int it = 0; it < NCH; ++it) {
        int nxt = (cur == STAGES - 1) ? 0 : cur + 1;
        int nxt2 = (nxt == STAGES - 1) ? 0 : nxt + 1;

        if (it + 2 < NCH) LOAD_A(nxt2, it + 2);
        CP_COMMIT();

        uint32_t aBase = A_BASE(cur);
        uint32_t bBase = B_BASE(cur);
        uint32_t bb = B_BASE(nxt);

        bool hn = (it + 1 < NCH);
        const int* wp = wqt + (size_t)(it + 1) * TILE_K;
        float s = 0.f;
        int4 q0, q1, q2, q3;
        if (hn) {
            s = wsp[(it + 1) >> 1];
            q0 = *reinterpret_cast<const int4*>(wp);
            q1 = *reinterpret_cast<const int4*>(wp + 1 * WROW);
            q2 = *reinterpret_cast<const int4*>(wp + 2 * WROW);
            q3 = *reinterpret_cast<const int4*>(wp + 3 * WROW);
        }

        COMPUTE_KS(0);
        if (hn) {
            cvt_sts(bb + sw128(bsts + 0 * 2048), q0, s);
            cvt_sts(bb + sw128(bsts + 1 * 2048), q1, s);
            q0 = *reinterpret_cast<const int4*>(wp + 4 * WROW);
            q1 = *reinterpret_cast<const int4*>(wp + 5 * WROW);
        }
        COMPUTE_KS(1);
        if (hn) {
            cvt_sts(bb + sw128(bsts + 2 * 2048), q2, s);
            cvt_sts(bb + sw128(bsts + 3 * 2048), q3, s);
            q2 = *reinterpret_cast<const int4*>(wp + 6 * WROW);
            q3 = *reinterpret_cast<const int4*>(wp + 7 * WROW);
        }
        COMPUTE_KS(2);
        if (hn) {
            cvt_sts(bb + sw128(bsts + 4 * 2048), q0, s);
            cvt_sts(bb + sw128(bsts + 5 * 2048), q1, s);
        }
        COMPUTE_KS(3);
        if (hn) {
            cvt_sts(bb + sw128(bsts + 6 * 2048), q2, s);
            cvt_sts(bb + sw128(bsts + 7 * 2048), q3, s);
        }

        CP_WAIT1();
        __syncthreads();
        cur = nxt;
    }

    // ---- epilogue: fp32 direct ----
#pragma unroll
    for (int mi = 0; mi < 2; ++mi) {
#pragma unroll
        for (int ni = 0; ni < 8; ++ni) {
            int row = m0 + m_warp + mi * 16 + (lid >> 2);
            int col = n0 + n_warp + ni * 8 + ((lid & 3) << 1);
            float2 v0 = make_float2(acc[mi][ni][0], acc[mi][ni][1]);
            float2 v1 = make_float2(acc[mi][ni][2], acc[mi][ni][3]);
            *reinterpret_cast<float2*>(out + (size_t)row * N_OUT + col) = v0;
            *reinterpret_cast<float2*>(out + (size_t)(row + 8) * N_OUT + col) = v1;
        }
    }
}

// ---------------------------------------------------------------------------
// Launch
// ---------------------------------------------------------------------------
extern "C" void kernel_launch(void* const* d_in, const int* in_sizes, int n_in,
                              void* d_out, int out_size) {
    const float* x  = (const float*)d_in[0];
    const int*   wq = (const int*)d_in[1];     // int8 widened to int32 by harness
    const float* ws = (const float*)d_in[2];
    float* out = (float*)d_out;

    cvt_x_kernel<<<2048, 256>>>(x);

    cudaFuncSetAttribute(gemm_fused_kernel,
                         cudaFuncAttributeMaxDynamicSharedMemorySize, SMEM_TOTAL);
    dim3 grid(N_OUT / TILE_N, M_ROWS / TILE_M);  // (64, 4) = 256 CTAs
    gemm_fused_kernel<<<grid, 256, SMEM_TOTAL>>>(wq, ws, out);
}

// round 10
// speedup vs baseline: 1.2394x; 1.1507x over previous
#include <cuda_runtime.h>
#include <cuda_fp16.h>
#include <cstdint>
#include <cstddef>

// ---------------------------------------------------------------------------
// Problem constants
// ---------------------------------------------------------------------------
#define M_ROWS 512
#define N_OUT  8192
#define K_IN   8192

#define TILE_M 128
#define TILE_N 128
#define TILE_K 64                     // K elements per stage
#define NCHUNK (K_IN / TILE_K)        // 128
#define STAGES 3

#define A_STAGE_BYTES (TILE_M * TILE_K * 2)   // 16384 fp16, swizzled
#define B_STAGE_BYTES (TILE_N * TILE_K * 2)   // 16384 fp16, swizzled
#define STAGE_BYTES (A_STAGE_BYTES + B_STAGE_BYTES)
#define SMEM_TOTAL (STAGES * STAGE_BYTES)     // 98304

// ---------------------------------------------------------------------------
// Scratch (device globals: allocation-free rule)
// ---------------------------------------------------------------------------
__device__ __half g_xh[(size_t)M_ROWS * K_IN];   // 8 MB fp16 x
__device__ __half g_wh[(size_t)N_OUT * K_IN];    // 128 MB fp16 dequantized W

// ---------------------------------------------------------------------------
// Helpers
// ---------------------------------------------------------------------------
__device__ __forceinline__ uint32_t smem_u32(const void* p) {
    uint32_t a;
    asm("{ .reg .u64 t; cvta.to.shared.u64 t, %1; cvt.u32.u64 %0, t; }"
        : "=r"(a) : "l"(p));
    return a;
}

__device__ __forceinline__ uint32_t sw128(uint32_t off) {
    return off ^ ((off >> 3) & 0x70);
}

__device__ __forceinline__ void cp_async16(uint32_t dst, const void* src) {
    asm volatile("cp.async.cg.shared.global [%0], [%1], 16;\n"
                 :: "r"(dst), "l"(src) : "memory");
}
#define CP_COMMIT() asm volatile("cp.async.commit_group;\n" ::: "memory")
#define CP_WAIT1()  asm volatile("cp.async.wait_group 1;\n" ::: "memory")

__device__ __forceinline__ void ldmatrix_x4(uint32_t* r, uint32_t addr) {
    asm volatile("ldmatrix.sync.aligned.m8n8.x4.shared.b16 {%0,%1,%2,%3}, [%4];\n"
                 : "=r"(r[0]), "=r"(r[1]), "=r"(r[2]), "=r"(r[3]) : "r"(addr));
}

__device__ __forceinline__ void mma16816(float* c, const uint32_t* a,
                                         uint32_t b0, uint32_t b1) {
    asm volatile(
        "mma.sync.aligned.m16n8k16.row.col.f32.f16.f16.f32 "
        "{%0,%1,%2,%3}, {%4,%5,%6,%7}, {%8,%9}, {%0,%1,%2,%3};\n"
        : "+f"(c[0]), "+f"(c[1]), "+f"(c[2]), "+f"(c[3])
        : "r"(a[0]), "r"(a[1]), "r"(a[2]), "r"(a[3]), "r"(b0), "r"(b1));
}

// ---------------------------------------------------------------------------
// Kernel 1: x fp32 -> fp16
// ---------------------------------------------------------------------------
__global__ void __launch_bounds__(256) cvt_x_kernel(const float* __restrict__ x) {
    size_t t = (size_t)blockIdx.x * 256 + threadIdx.x;
    size_t base = t * 8;
    float4 a = *reinterpret_cast<const float4*>(x + base);
    float4 b = *reinterpret_cast<const float4*>(x + base + 4);
    __align__(16) __half h[8];
    h[0] = __float2half_rn(a.x); h[1] = __float2half_rn(a.y);
    h[2] = __float2half_rn(a.z); h[3] = __float2half_rn(a.w);
    h[4] = __float2half_rn(b.x); h[5] = __float2half_rn(b.y);
    h[6] = __float2half_rn(b.z); h[7] = __float2half_rn(b.w);
    *reinterpret_cast<uint4*>(g_xh + base) = *reinterpret_cast<uint4*>(h);
}

// ---------------------------------------------------------------------------
// Kernel 2: dequant W (int32-widened int8 * block scale) -> fp16
// ---------------------------------------------------------------------------
__global__ void __launch_bounds__(256) dequant_w_kernel(
    const int* __restrict__ wq, const float* __restrict__ ws) {
    size_t t = (size_t)blockIdx.x * 256 + threadIdx.x;
    size_t base = t * 8;
    int o = (int)(base >> 13);           // out feature
    int i = (int)(base & (K_IN - 1));    // in feature
    float s = ws[(o >> 7) * (K_IN / 128) + (i >> 7)];
    int4 a = *reinterpret_cast<const int4*>(wq + base);
    int4 b = *reinterpret_cast<const int4*>(wq + base + 4);
    __align__(16) __half h[8];
    h[0] = __float2half_rn(s * (float)a.x);
    h[1] = __float2half_rn(s * (float)a.y);
    h[2] = __float2half_rn(s * (float)a.z);
    h[3] = __float2half_rn(s * (float)a.w);
    h[4] = __float2half_rn(s * (float)b.x);
    h[5] = __float2half_rn(s * (float)b.y);
    h[6] = __float2half_rn(s * (float)b.z);
    h[7] = __float2half_rn(s * (float)b.w);
    *reinterpret_cast<uint4*>(g_wh + base) = *reinterpret_cast<uint4*>(h);
}

// ---------------------------------------------------------------------------
// Kernel 3: fp16 GEMM (mma.sync), 3-stage cp.async pipeline, 2 CTAs/SM.
//   Inner loop: A-fragment double-buffering + cp.async spread over ks steps.
// ---------------------------------------------------------------------------
__global__ void __launch_bounds__(256, 2) gemm_kernel(float* __restrict__ out) {
    extern __shared__ char smem[];
    uint32_t sb = smem_u32(smem);
    int tid = threadIdx.x;
    int lid = tid & 31;
    int wid = tid >> 5;
    int m_warp = (wid >> 1) * 32;             // 4x2 warp grid
    int n_warp = (wid & 1) * 64;              // warp tile 32m x 64n

    int n0 = blockIdx.x * TILE_N;
    int m0 = blockIdx.y * TILE_M;

    const __half* xh = g_xh;
    const __half* wh = g_wh;

    // loader mapping: per sweep i, thread covers (row = tid/8 + 32i, col = tid%8)
    int arow = tid >> 3, acol = tid & 7;
    uint32_t lsts = sw128((uint32_t)arow * 128 + acol * 16);   // +4096*i exact
    const __half* xp = xh + (size_t)(m0 + arow) * K_IN + acol * 8;
    const __half* wp = wh + (size_t)(n0 + arow) * K_IN + acol * 8;

#define A_BASE(st) (sb + (uint32_t)(st) * STAGE_BYTES)
#define B_BASE(st) (sb + (uint32_t)(st) * STAGE_BYTES + A_STAGE_BYTES)

    // one (A,B) cp.async pair, sweep i of chunk -> stage st
#define LOAD_PAIR(st, chunk, i) do {                                          \
    size_t _k = (size_t)(chunk) * TILE_K + (size_t)(i) * 32 * K_IN;           \
    uint32_t _o = lsts + (uint32_t)(i) * 4096;                                \
    cp_async16(A_BASE(st) + _o, xp + _k);                                     \
    cp_async16(B_BASE(st) + _o, wp + _k);                                     \
} while (0)

#define LOAD_STAGE(st, chunk) do {                                            \
    LOAD_PAIR(st, chunk, 0); LOAD_PAIR(st, chunk, 1);                         \
    LOAD_PAIR(st, chunk, 2); LOAD_PAIR(st, chunk, 3);                         \
} while (0)

    // A-fragment fetch for one (mi, ks)
#define LDSM_A(dst, ks) do {                                                  \
    uint32_t o0 = (uint32_t)(m_warp + (lid & 15)) * 128                       \
                + (ks) * 32 + ((lid >> 4) << 4);                              \
    ldmatrix_x4((dst)[0], aBase + sw128(o0));                                 \
    ldmatrix_x4((dst)[1], aBase + sw128(o0 + 16 * 128));                      \
} while (0)

    float acc[2][8][4];
#pragma unroll
    for (int mi = 0; mi < 2; ++mi)
#pragma unroll
        for (int ni = 0; ni < 8; ++ni)
#pragma unroll
            for (int j = 0; j < 4; ++j) acc[mi][ni][j] = 0.f;

    // ---- prologue: stages 0,1 in flight ----
    LOAD_STAGE(0, 0);
    CP_COMMIT();
    LOAD_STAGE(1, 1);
    CP_COMMIT();
    CP_WAIT1();              // stage 0 landed
    __syncthreads();

    // ---- main loop ----
    int cur = 0, nxt2 = 2;
#pragma unroll 1
    for (int it = 0; it < NCHUNK; ++it) {
        uint32_t aBase = A_BASE(cur);
        uint32_t bBase = B_BASE(cur);
        bool pf = (it + 2 < NCHUNK);

        uint32_t af[2][2][4];            // [buf][mi][4]
        LDSM_A(af[0], 0);

#pragma unroll
        for (int ks = 0; ks < 4; ++ks) {
            int b = ks & 1;
            if (ks < 3) LDSM_A(af[b ^ 1], ks + 1);
            if (pf) { LOAD_PAIR(nxt2, it + 2, ks); }
#pragma unroll
            for (int ntl = 0; ntl < 4; ++ntl) {
                uint32_t r[4];
                uint32_t off = (uint32_t)(n_warp + ntl * 16 + (lid & 7)
                                          + ((lid >> 4) << 3)) * 128
                             + ks * 32 + (((lid >> 3) & 1) << 4);
                ldmatrix_x4(r, bBase + sw128(off));
#pragma unroll
                for (int mi = 0; mi < 2; ++mi) {
                    mma16816(acc[mi][2 * ntl],     af[b][mi], r[0], r[1]);
                    mma16816(acc[mi][2 * ntl + 1], af[b][mi], r[2], r[3]);
                }
            }
        }

        CP_COMMIT();
        CP_WAIT1();          // next stage landed
        __syncthreads();

        cur = (cur == STAGES - 1) ? 0 : cur + 1;
        nxt2 = (nxt2 == STAGES - 1) ? 0 : nxt2 + 1;
    }

    // ---- epilogue ----
#pragma unroll
    for (int mi = 0; mi < 2; ++mi) {
#pragma unroll
        for (int ni = 0; ni < 8; ++ni) {
            int row = m0 + m_warp + mi * 16 + (lid >> 2);
            int col = n0 + n_warp + ni * 8 + ((lid & 3) << 1);
            float2 v0 = make_float2(acc[mi][ni][0], acc[mi][ni][1]);
            float2 v1 = make_float2(acc[mi][ni][2], acc[mi][ni][3]);
            *reinterpret_cast<float2*>(out + (size_t)row * N_OUT + col) = v0;
            *reinterpret_cast<float2*>(out + (size_t)(row + 8) * N_OUT + col) = v1;
        }
    }
}

// ---------------------------------------------------------------------------
// Launch
// ---------------------------------------------------------------------------
extern "C" void kernel_launch(void* const* d_in, const int* in_sizes, int n_in,
                              void* d_out, int out_size) {
    const float* x  = (const float*)d_in[0];
    const int*   wq = (const int*)d_in[1];     // int8 widened to int32 by harness
    const float* ws = (const float*)d_in[2];
    float* out = (float*)d_out;

    cvt_x_kernel<<<2048, 256>>>(x);
    dequant_w_kernel<<<32768, 256>>>(wq, ws);

    cudaFuncSetAttribute(gemm_kernel,
                         cudaFuncAttributeMaxDynamicSharedMemorySize, SMEM_TOTAL);
    dim3 grid(N_OUT / TILE_N, M_ROWS / TILE_M);  // (64, 4) = 256 CTAs
    gemm_kernel<<<grid, 256, SMEM_TOTAL>>>(out);
}

// round 11
// speedup vs baseline: 1.4114x; 1.1387x over previous
#include <cuda_runtime.h>
#include <cuda_fp16.h>
#include <cstdint>
#include <cstddef>

// ---------------------------------------------------------------------------
// Problem constants
// ---------------------------------------------------------------------------
#define M_ROWS 512
#define N_OUT  8192
#define K_IN   8192

#define TILE_M 128
#define TILE_N 128
#define TILE_K 64                     // K elements per stage
#define KSPLIT 4
#define K_UNIT (K_IN / KSPLIT)        // 2048
#define NCH    (K_UNIT / TILE_K)      // 32 chunks per unit
#define STAGES 3

#define A_STAGE_BYTES (TILE_M * TILE_K * 2)   // 16384 fp16, swizzled
#define B_STAGE_BYTES (TILE_N * TILE_K * 2)   // 16384 fp16, swizzled
#define STAGE_BYTES (A_STAGE_BYTES + B_STAGE_BYTES)
#define SMEM_TOTAL (STAGES * STAGE_BYTES)     // 98304

// ---------------------------------------------------------------------------
// Scratch (device globals: allocation-free rule)
// ---------------------------------------------------------------------------
__device__ __half g_xh[(size_t)M_ROWS * K_IN];               // 8 MB fp16 x
__device__ __half g_wh[(size_t)N_OUT * K_IN];                // 128 MB fp16 W
__device__ __half g_part[(size_t)KSPLIT * M_ROWS * N_OUT];   // 33.5 MB partials

// ---------------------------------------------------------------------------
// Helpers
// ---------------------------------------------------------------------------
__device__ __forceinline__ uint32_t smem_u32(const void* p) {
    uint32_t a;
    asm("{ .reg .u64 t; cvta.to.shared.u64 t, %1; cvt.u32.u64 %0, t; }"
        : "=r"(a) : "l"(p));
    return a;
}

__device__ __forceinline__ uint32_t sw128(uint32_t off) {
    return off ^ ((off >> 3) & 0x70);
}

__device__ __forceinline__ void cp_async16(uint32_t dst, const void* src) {
    asm volatile("cp.async.cg.shared.global [%0], [%1], 16;\n"
                 :: "r"(dst), "l"(src) : "memory");
}
#define CP_COMMIT() asm volatile("cp.async.commit_group;\n" ::: "memory")
#define CP_WAIT1()  asm volatile("cp.async.wait_group 1;\n" ::: "memory")

__device__ __forceinline__ void ldmatrix_x4(uint32_t* r, uint32_t addr) {
    asm volatile("ldmatrix.sync.aligned.m8n8.x4.shared.b16 {%0,%1,%2,%3}, [%4];\n"
                 : "=r"(r[0]), "=r"(r[1]), "=r"(r[2]), "=r"(r[3]) : "r"(addr));
}

__device__ __forceinline__ void mma16816(float* c, const uint32_t* a,
                                         const uint32_t* b) {
    asm volatile(
        "mma.sync.aligned.m16n8k16.row.col.f32.f16.f16.f32 "
        "{%0,%1,%2,%3}, {%4,%5,%6,%7}, {%8,%9}, {%0,%1,%2,%3};\n"
        : "+f"(c[0]), "+f"(c[1]), "+f"(c[2]), "+f"(c[3])
        : "r"(a[0]), "r"(a[1]), "r"(a[2]), "r"(a[3]), "r"(b[0]), "r"(b[1]));
}

// ---------------------------------------------------------------------------
// Kernel 1: x fp32 -> fp16
// ---------------------------------------------------------------------------
__global__ void __launch_bounds__(256) cvt_x_kernel(const float* __restrict__ x) {
    size_t t = (size_t)blockIdx.x * 256 + threadIdx.x;
    size_t base = t * 8;
    float4 a = *reinterpret_cast<const float4*>(x + base);
    float4 b = *reinterpret_cast<const float4*>(x + base + 4);
    __align__(16) __half h[8];
    h[0] = __float2half_rn(a.x); h[1] = __float2half_rn(a.y);
    h[2] = __float2half_rn(a.z); h[3] = __float2half_rn(a.w);
    h[4] = __float2half_rn(b.x); h[5] = __float2half_rn(b.y);
    h[6] = __float2half_rn(b.z); h[7] = __float2half_rn(b.w);
    *reinterpret_cast<uint4*>(g_xh + base) = *reinterpret_cast<uint4*>(h);
}

// ---------------------------------------------------------------------------
// Kernel 2: dequant W (int32-widened int8 * block scale) -> fp16
// ---------------------------------------------------------------------------
__global__ void __launch_bounds__(256) dequant_w_kernel(
    const int* __restrict__ wq, const float* __restrict__ ws) {
    size_t t = (size_t)blockIdx.x * 256 + threadIdx.x;
    size_t base = t * 8;
    int o = (int)(base >> 13);           // out feature
    int i = (int)(base & (K_IN - 1));    // in feature
    float s = ws[(o >> 7) * (K_IN / 128) + (i >> 7)];
    int4 a = *reinterpret_cast<const int4*>(wq + base);
    int4 b = *reinterpret_cast<const int4*>(wq + base + 4);
    __align__(16) __half h[8];
    h[0] = __float2half_rn(s * (float)a.x);
    h[1] = __float2half_rn(s * (float)a.y);
    h[2] = __float2half_rn(s * (float)a.z);
    h[3] = __float2half_rn(s * (float)a.w);
    h[4] = __float2half_rn(s * (float)b.x);
    h[5] = __float2half_rn(s * (float)b.y);
    h[6] = __float2half_rn(s * (float)b.z);
    h[7] = __float2half_rn(s * (float)b.w);
    *reinterpret_cast<uint4*>(g_wh + base) = *reinterpret_cast<uint4*>(h);
}

// ---------------------------------------------------------------------------
// Kernel 3: fp16 GEMM (mma.sync), 3-stage cp.async pipeline, 2 CTAs/SM,
//   split-K x4 for load balance. Inner loop verbatim from the R5 best.
//   grid = 1024: bid -> (mt 0..3 fastest, kq 0..3, nt 0..63)
// ---------------------------------------------------------------------------
__global__ void __launch_bounds__(256, 2) gemm_kernel(void) {
    extern __shared__ char smem[];
    uint32_t sb = smem_u32(smem);
    int tid = threadIdx.x;
    int lid = tid & 31;
    int wid = tid >> 5;
    int wm = wid >> 1, wn = wid & 1;          // 4x2 warp grid
    int m_warp = wm * 32, n_warp = wn * 64;   // warp tile 32m x 64n

    int bid = blockIdx.x;
    int mt = bid & 3;
    int kq = (bid >> 2) & 3;
    int nt = bid >> 4;
    int m0 = mt * TILE_M;
    int n0 = nt * TILE_N;
    int kbase = kq * K_UNIT;

    const __half* xh = g_xh;
    const __half* wh = g_wh;

    float acc[2][8][4];
#pragma unroll
    for (int mi = 0; mi < 2; ++mi)
#pragma unroll
        for (int ni = 0; ni < 8; ++ni)
#pragma unroll
            for (int j = 0; j < 4; ++j) acc[mi][ni][j] = 0.f;

    // A/B load: 4 x 16B segments per thread each, swizzled fp16 tiles
#define LOAD_STAGE(slot, chunk) do {                                          \
    int k0h = kbase + (chunk) * TILE_K;                                       \
    uint32_t ab = sb + (uint32_t)(slot) * STAGE_BYTES;                        \
    uint32_t bb = ab + A_STAGE_BYTES;                                         \
    _Pragma("unroll")                                                         \
    for (int i = 0; i < 4; ++i) {                                             \
        int seg = tid + i * 256;                                              \
        int row = seg >> 3, c = seg & 7;                                      \
        cp_async16(ab + sw128((uint32_t)row * 128 + c * 16),                  \
                   xh + (size_t)(m0 + row) * K_IN + k0h + c * 8);             \
        cp_async16(bb + sw128((uint32_t)row * 128 + c * 16),                  \
                   wh + (size_t)(n0 + row) * K_IN + k0h + c * 8);             \
    }                                                                         \
} while (0)

    // ---- prologue: stages 0,1 in flight ----
    LOAD_STAGE(0, 0);
    CP_COMMIT();
    LOAD_STAGE(1, 1);
    CP_COMMIT();
    CP_WAIT1();              // stage 0 landed
    __syncthreads();

    // ---- main loop (verbatim R5 structure) ----
    int cur = 0, nxt2 = 2;
#pragma unroll 1
    for (int it = 0; it < NCH; ++it) {
        if (it + 2 < NCH) LOAD_STAGE(nxt2, it + 2);
        CP_COMMIT();

        uint32_t aBase = sb + (uint32_t)cur * STAGE_BYTES;
        uint32_t bBase = aBase + A_STAGE_BYTES;

#pragma unroll
        for (int ks = 0; ks < 4; ++ks) {
            uint32_t af[2][4];
#pragma unroll
            for (int mi = 0; mi < 2; ++mi) {
                uint32_t off = (uint32_t)(m_warp + mi * 16 + (lid & 15)) * 128
                             + ks * 32 + ((lid >> 4) << 4);
                ldmatrix_x4(af[mi], aBase + sw128(off));
            }
            uint32_t bf[8][2];
#pragma unroll
            for (int ntl = 0; ntl < 4; ++ntl) {
                uint32_t r[4];
                uint32_t off = (uint32_t)(n_warp + ntl * 16 + (lid & 7)
                                          + ((lid >> 4) << 3)) * 128
                             + ks * 32 + (((lid >> 3) & 1) << 4);
                ldmatrix_x4(r, bBase + sw128(off));
                bf[2 * ntl][0] = r[0]; bf[2 * ntl][1] = r[1];
                bf[2 * ntl + 1][0] = r[2]; bf[2 * ntl + 1][1] = r[3];
            }
#pragma unroll
            for (int mi = 0; mi < 2; ++mi)
#pragma unroll
                for (int ni = 0; ni < 8; ++ni)
                    mma16816(acc[mi][ni], af[mi], bf[ni]);
        }

        CP_WAIT1();          // next stage landed
        __syncthreads();

        cur = (cur == STAGES - 1) ? 0 : cur + 1;
        nxt2 = (nxt2 == STAGES - 1) ? 0 : nxt2 + 1;
    }

    // ---- epilogue: fp16 partials -> g_part[kq] ----
    __half* pout = g_part + (size_t)kq * ((size_t)M_ROWS * N_OUT);
#pragma unroll
    for (int mi = 0; mi < 2; ++mi) {
#pragma unroll
        for (int ni = 0; ni < 8; ++ni) {
            int row = m0 + m_warp + mi * 16 + (lid >> 2);
            int col = n0 + n_warp + ni * 8 + ((lid & 3) << 1);
            __half2 v0 = __floats2half2_rn(acc[mi][ni][0], acc[mi][ni][1]);
            __half2 v1 = __floats2half2_rn(acc[mi][ni][2], acc[mi][ni][3]);
            *reinterpret_cast<__half2*>(pout + (size_t)row * N_OUT + col) = v0;
            *reinterpret_cast<__half2*>(pout + (size_t)(row + 8) * N_OUT + col) = v1;
        }
    }
}

// ---------------------------------------------------------------------------
// Kernel 4: reduce 4 fp16 partials -> fp32 out
// ---------------------------------------------------------------------------
__global__ void __launch_bounds__(256) reduce_kernel(float* __restrict__ out) {
    size_t t = (size_t)blockIdx.x * 256 + threadIdx.x;
    size_t base = t * 8;
    const size_t SZ = (size_t)M_ROWS * N_OUT;
    float r[8];
#pragma unroll
    for (int j = 0; j < 8; ++j) r[j] = 0.f;
#pragma unroll
    for (int kq = 0; kq < KSPLIT; ++kq) {
        uint4 v = *reinterpret_cast<const uint4*>(g_part + kq * SZ + base);
        const __half2* h = reinterpret_cast<const __half2*>(&v);
#pragma unroll
        for (int j = 0; j < 4; ++j) {
            float2 f = __half22float2(h[j]);
            r[2 * j] += f.x;
            r[2 * j + 1] += f.y;
        }
    }
    float4 o0 = make_float4(r[0], r[1], r[2], r[3]);
    float4 o1 = make_float4(r[4], r[5], r[6], r[7]);
    *reinterpret_cast<float4*>(out + base) = o0;
    *reinterpret_cast<float4*>(out + base + 4) = o1;
}

// ---------------------------------------------------------------------------
// Launch
// ---------------------------------------------------------------------------
extern "C" void kernel_launch(void* const* d_in, const int* in_sizes, int n_in,
                              void* d_out, int out_size) {
    const float* x  = (const float*)d_in[0];
    const int*   wq = (const int*)d_in[1];     // int8 widened to int32 by harness
    const float* ws = (const float*)d_in[2];
    float* out = (float*)d_out;

    cvt_x_kernel<<<2048, 256>>>(x);
    dequant_w_kernel<<<32768, 256>>>(wq, ws);

    cudaFuncSetAttribute(gemm_kernel,
                         cudaFuncAttributeMaxDynamicSharedMemorySize, SMEM_TOTAL);
    // 1024 units: 4 mt (fastest) x 4 kq x 64 nt
    gemm_kernel<<<1024, 256, SMEM_TOTAL>>>();

    // 512*8192 / 8 / 256 = 2048 blocks
    reduce_kernel<<<2048, 256>>>(out);
}